// round 13
// baseline (speedup 1.0000x reference)
#include <cuda_runtime.h>

// BoxFilterND: truncated 2D box SUM, radius 8, over dims 2,3 of (8,32,512,512) fp32.
// out[r][c] = sum_{dr=-8..8, dc=-8..8, in-bounds} in[r+dr][c+dc]
//
// R9 design (from R8 profile: L1tex 67.4% = bottleneck, DRAM 55.3%, issue 41.8%):
//   - NO smem ring: trailing row (r-9) re-loaded from global; it was streamed
//     ~2 batches ago -> L2 hit (chip-wide recency window ~20 MB << 126 MB L2).
//     Input loads use DEFAULT caching (retention matters); output uses __stcs
//     (never re-read, don't evict the L2 reuse window).
//   - RB=8 batches; vbuf split into even/odd column halves so the 8-output-per-thread
//     horizontal pass reads 3+3 dense LDS.128 (16B stride, conflict-free) instead of
//     a 32B-strided (2x bank conflict) layout. Odd half at float offset 272 -> vertical
//     STS from even/odd lanes land on disjoint banks (verified: banks 4..19 / 20..3).
//   - Horizontal: outputs 8t..8t+7 from 24-float window via sliding +/- (30 FADD).
// Grid: 256 planes x 4 chunks of 128 rows = 1024 CTAs. Block: 512 threads.

#define NP    512
#define W     512
#define RAD   8
#define WIN   17
#define CHUNK 128
#define RB    8
#define EO    272          // float offset of odd-column half within a vbuf row
#define VROW  536          // floats per row: [4 pad | 256 even | 4 pad | @272: 4 pad | 256 odd | 4 pad]

__global__ __launch_bounds__(512)
void boxfilter2d_kernel(const float* __restrict__ in, float* __restrict__ out) {
    __shared__ __align__(16) float vb[RB][VROW];

    const int c     = threadIdx.x;
    const int plane = blockIdx.x >> 2;
    const int chunk = blockIdx.x & 3;
    const int r0    = chunk * CHUNK;

    const float* __restrict__ pin  = in  + (size_t)plane * (NP * W);
    float*       __restrict__ pout = out + (size_t)plane * (NP * W);

    // Vertical store slot: parity-split. col c -> half (c&1), index (c>>1).
    const int vidx = ((c & 1) ? EO : 0) + 4 + (c >> 1);

    // Horizontal role: row g (0..7), 64 threads per row, 8 outputs each (cols 8t..8t+7).
    const int g = c >> 6;
    const int t = c & 63;

    // Zero the halo pads once: per row, e[0..3], e[260..263], o[0..3], o[260..263].
    if (c < 128) {
        int rr = c >> 4, k = c & 15;
        int idx = (k < 4)  ? k
                : (k < 8)  ? 256 + k            // 260..263
                : (k < 12) ? EO + (k - 8)       // EO+0..3
                           : EO + 248 + k;      // EO+260..263
        vb[rr][idx] = 0.f;
    }

    // ---- Prologue: sv = sum of rows [r0-9, r0+7] (guarded; max row 391 < 512).
    float sv = 0.f;
    #pragma unroll
    for (int i = 0; i < WIN; ++i) {
        int k = r0 - (RAD + 1) + i;
        sv += (k >= 0) ? pin[k * W + c] : 0.f;
    }

    for (int rb = 0; rb < CHUNK; rb += RB) {
        // ---- Vertical: batch loads first (16 independent LDG -> high MLP),
        //      then the serial sliding-sum chain.
        float lead[RB], trail[RB];
        #pragma unroll
        for (int rr = 0; rr < RB; ++rr) {
            int r = r0 + rb + rr;
            int L = r + RAD;                    // leading row (DRAM stream)
            int T = r - (RAD + 1);              // trailing row (recent -> L2 hit)
            lead[rr]  = (L < NP)  ? pin[L * W + c] : 0.f;
            trail[rr] = (T >= 0)  ? pin[T * W + c] : 0.f;
        }
        #pragma unroll
        for (int rr = 0; rr < RB; ++rr) {
            sv += lead[rr] - trail[rr];
            vb[rr][vidx] = sv;                  // vertical box sum, this row, col c
        }
        __syncthreads();

        // ---- Horizontal: outputs 8t..8t+7 of row (rb+g).
        // Window cols [8t-8, 8t+15] = even idx [4t-4,4t+7] (+4 pad -> vb[4t..4t+11])
        //                           + odd  idx [4t-4,4t+7] (-> vb[EO+4t..EO+4t+11])
        {
            const float* vr = vb[g];
            float4 E0 = *(const float4*)&vr[4 * t];
            float4 E1 = *(const float4*)&vr[4 * t + 4];
            float4 E2 = *(const float4*)&vr[4 * t + 8];
            float4 O0 = *(const float4*)&vr[EO + 4 * t];
            float4 O1 = *(const float4*)&vr[EO + 4 * t + 4];
            float4 O2 = *(const float4*)&vr[EO + 4 * t + 8];

            // s0 = sum evens E[0..8] + odds O[0..7]  (cols 8t-8 .. 8t+8)
            float s0 = ((E0.x + E0.y) + (E0.z + E0.w))
                     + ((E1.x + E1.y) + (E1.z + E1.w)) + E2.x
                     + ((O0.x + O0.y) + (O0.z + O0.w))
                     + ((O1.x + O1.y) + (O1.z + O1.w));
            float s1 = s0 - E0.x + O2.x;   // +col 8t+9 , -col 8t-8
            float s2 = s1 - O0.x + E2.y;   // +col 8t+10, -col 8t-7
            float s3 = s2 - E0.y + O2.y;
            float s4 = s3 - O0.y + E2.z;
            float s5 = s4 - E0.z + O2.z;
            float s6 = s5 - O0.z + E2.w;
            float s7 = s6 - E0.w + O2.w;

            float* po = &pout[(size_t)(r0 + rb + g) * W + 8 * t];
            float4 a; a.x = s0; a.y = s1; a.z = s2; a.w = s3;
            float4 b; b.x = s4; b.y = s5; b.z = s6; b.w = s7;
            __stcs((float4*)po,       a);
            __stcs((float4*)(po + 4), b);
        }
        __syncthreads();   // vb consumed before next batch overwrites it
    }
}

extern "C" void kernel_launch(void* const* d_in, const int* in_sizes, int n_in,
                              void* d_out, int out_size) {
    const float* in = (const float*)d_in[0];
    float* out = (float*)d_out;
    // 256 planes x 4 chunks of 128 rows
    boxfilter2d_kernel<<<1024, 512>>>(in, out);
}